// round 13
// baseline (speedup 1.0000x reference)
#include <cuda_runtime.h>
#include <cuda_fp16.h>
#include <cstdint>
#include <math.h>

#define BB 64
#define TT 1024
#define HH 512
#define G3 1536
#define HPAD 516

// ---------------- scratch (device globals; no runtime allocation) ----------------
__device__ float g_xg[(size_t)BB * TT * G3];   // [B*T][1536] packed input-gate projections
__device__ float g_y0[(size_t)BB * TT * HH];   // [B*T][512] layer-0 tanh outputs
__device__ float g_h[2][BB * HH];              // ping-pong hidden state
__device__ __align__(16) unsigned g_cnt4[4][4];// 4 sub-counters per batch group (one sector)
__device__ unsigned g_done[4];                 // per-group completion counter

// ---------------- tf32 helpers (phase A) ----------------
__device__ __forceinline__ uint32_t to_tf32(float x) {
    uint32_t r;
    asm("cvt.rna.tf32.f32 %0, %1;" : "=r"(r) : "f"(x));
    return r;
}
#define MMA_TF32(d, a, b)                                                        \
    asm volatile("mma.sync.aligned.m16n8k8.row.col.f32.tf32.tf32.f32 "           \
                 "{%0,%1,%2,%3},{%4,%5,%6,%7},{%8,%9},{%0,%1,%2,%3};"            \
                 : "+f"((d)[0]), "+f"((d)[1]), "+f"((d)[2]), "+f"((d)[3])        \
                 : "r"((a)[0]), "r"((a)[1]), "r"((a)[2]), "r"((a)[3]),           \
                   "r"((b)[0]), "r"((b)[1]))

// ---------------- fp16 mma helper (phase R) ----------------
#define MMA_F16(d, a, b)                                                         \
    asm volatile("mma.sync.aligned.m16n8k16.row.col.f32.f16.f16.f32 "            \
                 "{%0,%1,%2,%3},{%4,%5,%6,%7},{%8,%9},{%0,%1,%2,%3};"            \
                 : "+f"((d)[0]), "+f"((d)[1]), "+f"((d)[2]), "+f"((d)[3])        \
                 : "r"((a)[0]), "r"((a)[1]), "r"((a)[2]), "r"((a)[3]),           \
                   "r"((b)[0]), "r"((b)[1]))

__device__ __forceinline__ unsigned poll_acq(const unsigned* p) {
    unsigned v;
    asm volatile("ld.acquire.gpu.global.u32 %0, [%1];" : "=r"(v) : "l"(p) : "memory");
    return v;
}
__device__ __forceinline__ unsigned long long ld_rlx64(const unsigned* p) {
    unsigned long long v;
    asm volatile("ld.relaxed.gpu.global.u64 %0, [%1];" : "=l"(v) : "l"(p) : "memory");
    return v;
}
// release-ordered increment: fence folded into the reduction op
__device__ __forceinline__ void red_release_add(unsigned* p, unsigned v) {
    asm volatile("red.release.gpu.global.add.u32 [%0], %1;" :: "l"(p), "r"(v) : "memory");
}
__device__ __forceinline__ void fence_acq() {
    asm volatile("fence.acq_rel.gpu;" ::: "memory");
}

// split a float2 into fp16x2 hi and lo (two-term split; residual exact)
__device__ __forceinline__ void split2(float2 v, uint32_t& hi, uint32_t& lo) {
    __half2 h2 = __floats2half2_rn(v.x, v.y);
    float2 hf = __half22float2(h2);
    __half2 l2 = __floats2half2_rn(v.x - hf.x, v.y - hf.y);
    hi = *(uint32_t*)&h2;
    lo = *(uint32_t*)&l2;
}

// ---------------- phase A: C[M,1536] = A[M,K] @ W[K,1536] + bias (tf32 MMA) ----------------
// Register prefetch + smem double-buffer: one __syncthreads per K-tile.
__global__ __launch_bounds__(256) void gemm_tf32(
    const float* __restrict__ A, const float* __restrict__ W,
    const float* __restrict__ bias, float* __restrict__ C, int K)
{
    __shared__ uint32_t As[2][128][20];
    __shared__ uint32_t Bs[2][16][136];

    const int tid = threadIdx.x;
    const int lane = tid & 31;
    const int wid = tid >> 5;
    const int wm = wid & 1;
    const int wn = wid >> 1;
    const int g = lane >> 2;
    const int c = lane & 3;
    const int bm = blockIdx.y * 128;
    const int bn = blockIdx.x * 128;

    const int ar = tid >> 1;
    const int ak = (tid & 1) * 8;
    const int br = tid >> 4;
    const int bc = (tid & 15) * 8;

    float acc[4][4][4];
#pragma unroll
    for (int mt = 0; mt < 4; ++mt)
#pragma unroll
        for (int nt = 0; nt < 4; ++nt)
#pragma unroll
            for (int i = 0; i < 4; ++i) acc[mt][nt][i] = 0.f;

    const float* ap = &A[(size_t)(bm + ar) * K + ak];
    const float* wp = &W[(size_t)br * G3 + bn + bc];

    // preload tile 0 into regs, store into buffer 0
    float4 a0 = *(const float4*)&ap[0];
    float4 a1 = *(const float4*)&ap[4];
    float4 b0 = *(const float4*)&wp[0];
    float4 b1 = *(const float4*)&wp[4];

    As[0][ar][ak + 0] = to_tf32(a0.x); As[0][ar][ak + 1] = to_tf32(a0.y);
    As[0][ar][ak + 2] = to_tf32(a0.z); As[0][ar][ak + 3] = to_tf32(a0.w);
    As[0][ar][ak + 4] = to_tf32(a1.x); As[0][ar][ak + 5] = to_tf32(a1.y);
    As[0][ar][ak + 6] = to_tf32(a1.z); As[0][ar][ak + 7] = to_tf32(a1.w);
    Bs[0][br][bc + 0] = to_tf32(b0.x); Bs[0][br][bc + 1] = to_tf32(b0.y);
    Bs[0][br][bc + 2] = to_tf32(b0.z); Bs[0][br][bc + 3] = to_tf32(b0.w);
    Bs[0][br][bc + 4] = to_tf32(b1.x); Bs[0][br][bc + 5] = to_tf32(b1.y);
    Bs[0][br][bc + 6] = to_tf32(b1.z); Bs[0][br][bc + 7] = to_tf32(b1.w);
    __syncthreads();

    for (int k0 = 0; k0 < K; k0 += 16) {
        const int buf = (k0 >> 4) & 1;
        const int nxt = buf ^ 1;
        const bool have_next = (k0 + 16 < K);

        // prefetch next tile (latency overlaps the MMA below)
        if (have_next) {
            a0 = *(const float4*)&ap[k0 + 16];
            a1 = *(const float4*)&ap[k0 + 20];
            b0 = *(const float4*)&wp[(size_t)(k0 + 16) * G3];
            b1 = *(const float4*)&wp[(size_t)(k0 + 16) * G3 + 4];
        }

#pragma unroll
        for (int kk = 0; kk < 2; ++kk) {
            uint32_t afr[4][4];
#pragma unroll
            for (int mt = 0; mt < 4; ++mt) {
                int arow = wm * 64 + mt * 16 + g;
                afr[mt][0] = As[buf][arow][kk * 8 + c];
                afr[mt][1] = As[buf][arow + 8][kk * 8 + c];
                afr[mt][2] = As[buf][arow][kk * 8 + c + 4];
                afr[mt][3] = As[buf][arow + 8][kk * 8 + c + 4];
            }
            uint32_t bfr[4][2];
#pragma unroll
            for (int nt = 0; nt < 4; ++nt) {
                int bcol = wn * 32 + nt * 8 + g;
                bfr[nt][0] = Bs[buf][kk * 8 + c][bcol];
                bfr[nt][1] = Bs[buf][kk * 8 + c + 4][bcol];
            }
#pragma unroll
            for (int mt = 0; mt < 4; ++mt)
#pragma unroll
                for (int nt = 0; nt < 4; ++nt)
                    MMA_TF32(acc[mt][nt], afr[mt], bfr[nt]);
        }

        // store prefetched tile into the other buffer, then one barrier
        if (have_next) {
            As[nxt][ar][ak + 0] = to_tf32(a0.x); As[nxt][ar][ak + 1] = to_tf32(a0.y);
            As[nxt][ar][ak + 2] = to_tf32(a0.z); As[nxt][ar][ak + 3] = to_tf32(a0.w);
            As[nxt][ar][ak + 4] = to_tf32(a1.x); As[nxt][ar][ak + 5] = to_tf32(a1.y);
            As[nxt][ar][ak + 6] = to_tf32(a1.z); As[nxt][ar][ak + 7] = to_tf32(a1.w);
            Bs[nxt][br][bc + 0] = to_tf32(b0.x); Bs[nxt][br][bc + 1] = to_tf32(b0.y);
            Bs[nxt][br][bc + 2] = to_tf32(b0.z); Bs[nxt][br][bc + 3] = to_tf32(b0.w);
            Bs[nxt][br][bc + 4] = to_tf32(b1.x); Bs[nxt][br][bc + 5] = to_tf32(b1.y);
            Bs[nxt][br][bc + 6] = to_tf32(b1.z); Bs[nxt][br][bc + 7] = to_tf32(b1.w);
            __syncthreads();
        }
    }

#pragma unroll
    for (int mt = 0; mt < 4; ++mt) {
        int r0 = bm + wm * 64 + mt * 16 + g;
#pragma unroll
        for (int nt = 0; nt < 4; ++nt) {
            int col = bn + wn * 32 + nt * 8 + 2 * c;
            float2 bv = *(const float2*)&bias[col];
            float2 v0 = make_float2(acc[mt][nt][0] + bv.x, acc[mt][nt][1] + bv.y);
            float2 v1 = make_float2(acc[mt][nt][2] + bv.x, acc[mt][nt][3] + bv.y);
            *(float2*)&C[(size_t)r0 * G3 + col] = v0;
            *(float2*)&C[(size_t)(r0 + 8) * G3 + col] = v1;
        }
    }
}

// ---------------- phase R: persistent GRU recurrence (fp16-split tensor cores) ----------------
// 128 CTAs = 4 batch-groups(16 batches) x 32 col-groups(16 output cols = 48 gate cols).
// Sync: 4 sub-counters per group (producer jg -> counter jg&3); lane-0 relaxed poll
// of the whole sector via two 64-bit loads; fence.acq_rel on exit.
#define SMEM_R ((16 * HPAD + 8 * 16 * 48) * 4)

__device__ __forceinline__ float sigf(float x) {
    return __fdividef(1.f, 1.f + __expf(-x));
}

__global__ __launch_bounds__(256, 1) void gru_rec(
    const float* __restrict__ Wh,    // [512][1536]
    const float* __restrict__ bhn,   // [512]
    const float* __restrict__ xg,    // [B*T][1536]
    float* __restrict__ y,           // [B*T][512] (y_all=1) or [B][512] last tanh (y_all=0)
    float* __restrict__ cfin,        // [64*512] final raw h
    int y_all)
{
    extern __shared__ __align__(16) float sm[];
    float* hs  = sm;                       // [16][HPAD] staged h (fp32)
    float* red = hs + 16 * HPAD;           // [8 kc][16 row][48 col]

    const int tid = threadIdx.x;
    const int cta = blockIdx.x;
    const int bg = cta >> 5;               // batch group 0..3
    const int jg = cta & 31;               // col group 0..31
    const int b0 = bg * 16;
    const int j0 = jg * 16;

    const int lane = tid & 31;
    const int kc = tid >> 5;               // warp id = K-chunk 0..7
    const int kb = kc * 64;
    const int g = lane >> 2;               // mma group row
    const int c = lane & 3;                // mma group col
    const int eb = tid >> 4;               // elementwise batch 0..15
    const int ej = tid & 15;               // elementwise col
    const float bh_n = bhn[j0 + ej];
    unsigned* my_cnt = &g_cnt4[bg][jg & 3];

    // ---- Precompute W_h fragments (hi/lo fp16) into registers.
    uint32_t bhi[6][4][2], blo[6][4][2];
#pragma unroll
    for (int nt = 0; nt < 6; ++nt) {
        int cl = nt * 8 + g;               // local col 0..47
        int wcol = (cl >> 4) * HH + j0 + (cl & 15);
#pragma unroll
        for (int kt = 0; kt < 4; ++kt) {
            int kbase = kb + kt * 16;
            float w0 = Wh[(size_t)(kbase + 2 * c) * G3 + wcol];
            float w1 = Wh[(size_t)(kbase + 2 * c + 1) * G3 + wcol];
            float w2 = Wh[(size_t)(kbase + 2 * c + 8) * G3 + wcol];
            float w3 = Wh[(size_t)(kbase + 2 * c + 9) * G3 + wcol];
            split2(make_float2(w0, w1), bhi[nt][kt][0], blo[nt][kt][0]);
            split2(make_float2(w2, w3), bhi[nt][kt][1], blo[nt][kt][1]);
        }
    }

    // Produce h^(0) = 0 for our own slice, publish like a normal step.
    g_h[0][(size_t)(b0 + eb) * HH + j0 + ej] = 0.f;
    __syncthreads();
    if (tid == 0) red_release_add(my_cnt, 1u);

    // Warp-private staging: warp kc stages hs[all 16 rows][kb..kb+64).
    const int sb = lane >> 1;
    const int sk = kb + (lane & 1) * 32;

    for (int t = 0; t < TT; ++t) {
        const float* hin = g_h[t & 1];
        float* hout = g_h[(t + 1) & 1];

        // xg prefetch (independent of h) — issued before the poll.
        size_t xi = ((size_t)(b0 + eb) * TT + t) * G3 + j0 + ej;
        float xr = __ldcs(&xg[xi]);
        float xz = __ldcs(&xg[xi + 512]);
        float xn = __ldcs(&xg[xi + 1024]);

        // Lane-0 relaxed poll of all 4 sub-counters (one sector, two 64-bit loads).
        unsigned target = 8u * (unsigned)(t + 1);
        if (lane == 0) {
            for (;;) {
                unsigned long long v01 = ld_rlx64(&g_cnt4[bg][0]);
                unsigned long long v23 = ld_rlx64(&g_cnt4[bg][2]);
                unsigned m = (unsigned)v01;
                unsigned x1 = (unsigned)(v01 >> 32); if (x1 < m) m = x1;
                unsigned x2 = (unsigned)v23;         if (x2 < m) m = x2;
                unsigned x3 = (unsigned)(v23 >> 32); if (x3 < m) m = x3;
                if (m >= target) break;
            }
        }
        __syncwarp();
        fence_acq();

        // Warp-private h staging (exactly the K-chunk this warp consumes).
        float4 hv0[8];
#pragma unroll
        for (int u = 0; u < 8; ++u)
            hv0[u] = __ldcg((const float4*)&hin[(size_t)(b0 + sb) * HH + sk + u * 4]);
#pragma unroll
        for (int u = 0; u < 8; ++u)
            *(float4*)&hs[sb * HPAD + sk + u * 4] = hv0[u];
        __syncwarp();

        // ---- tensor-core partial GEMM over K-chunk 64: acc[6 n-tiles][4].
        float acc[6][4];
#pragma unroll
        for (int nt = 0; nt < 6; ++nt)
#pragma unroll
            for (int i = 0; i < 4; ++i) acc[nt][i] = 0.f;

#pragma unroll
        for (int kt = 0; kt < 4; ++kt) {
            int k0 = kb + kt * 16;
            uint32_t ahi[4], alo[4];
            float2 p0 = *(const float2*)&hs[g * HPAD + k0 + 2 * c];
            float2 p1 = *(const float2*)&hs[(g + 8) * HPAD + k0 + 2 * c];
            float2 p2 = *(const float2*)&hs[g * HPAD + k0 + 2 * c + 8];
            float2 p3 = *(const float2*)&hs[(g + 8) * HPAD + k0 + 2 * c + 8];
            split2(p0, ahi[0], alo[0]);
            split2(p1, ahi[1], alo[1]);
            split2(p2, ahi[2], alo[2]);
            split2(p3, ahi[3], alo[3]);
#pragma unroll
            for (int nt = 0; nt < 6; ++nt) {
                MMA_F16(acc[nt], ahi, bhi[nt][kt]);
                MMA_F16(acc[nt], ahi, blo[nt][kt]);
                MMA_F16(acc[nt], alo, bhi[nt][kt]);
            }
        }

        // Write K-split partials.
#pragma unroll
        for (int nt = 0; nt < 6; ++nt) {
            int colb = nt * 8 + 2 * c;
            *(float2*)&red[(kc * 16 + g) * 48 + colb] =
                make_float2(acc[nt][0], acc[nt][1]);
            *(float2*)&red[(kc * 16 + g + 8) * 48 + colb] =
                make_float2(acc[nt][2], acc[nt][3]);
        }
        __syncthreads();

        // Elementwise GRU update: thread = (eb, ej).
        float hr = 0.f, hz = 0.f, hn = 0.f;
#pragma unroll
        for (int q = 0; q < 8; ++q) {
            const float* rp = &red[(q * 16 + eb) * 48];
            hr += rp[ej]; hz += rp[16 + ej]; hn += rp[32 + ej];
        }
        float h_old = hs[eb * HPAD + j0 + ej];
        float r = sigf(xr + hr);
        float z = sigf(xz + hz);
        float n = tanhf(xn + r * (hn + bh_n));
        float hnew = (1.f - z) * n + z * h_old;

        hout[(size_t)(b0 + eb) * HH + j0 + ej] = hnew;

        // Publish h^(t+1) (skip the dead final publish), then non-critical stores.
        __syncthreads();
        if (t < TT - 1 && tid == 0) red_release_add(my_cnt, 1u);

        if (y_all) {
            y[((size_t)(b0 + eb) * TT + t) * HH + j0 + ej] = tanhf(hnew);
        } else if (t == TT - 1) {
            y[(size_t)(b0 + eb) * HH + j0 + ej] = tanhf(hnew);
        }
        if (t == TT - 1)
            cfin[(size_t)(b0 + eb) * HH + j0 + ej] = hnew;
    }

    // ---- reset protocol for graph replay ----
    if (tid == 0) {
        red_release_add(&g_done[bg], 1u);
        if (jg == 0) {
            while (poll_acq(&g_done[bg]) < 32u) { }
            for (int q = 0; q < 4; ++q) g_cnt4[bg][q] = 0u;
            __threadfence();
            atomicExch(&g_done[bg], 0u);
        }
    }
}

// ---------------- dense head: out = tanh(ylast @ W_out + b_out) ----------------
__global__ __launch_bounds__(256) void dense_k(
    const float* __restrict__ yl,
    const float* __restrict__ W,
    const float* __restrict__ b,
    float* __restrict__ out)
{
    int gid = blockIdx.x * 256 + threadIdx.x;
    int bb = gid >> 9;
    int j  = gid & 511;
    const float* xr = yl + (size_t)bb * 512;
    float s = b[j];
#pragma unroll 4
    for (int k = 0; k < 512; k += 4) {
        float4 xv = *(const float4*)&xr[k];
        s = fmaf(xv.x, W[(size_t)(k + 0) * 512 + j], s);
        s = fmaf(xv.y, W[(size_t)(k + 1) * 512 + j], s);
        s = fmaf(xv.z, W[(size_t)(k + 2) * 512 + j], s);
        s = fmaf(xv.w, W[(size_t)(k + 3) * 512 + j], s);
    }
    out[gid] = tanhf(s);
}

// ---------------- launch ----------------
extern "C" void kernel_launch(void* const* d_in, const int* in_sizes, int n_in,
                              void* d_out, int out_size) {
    const float* x     = (const float*)d_in[0];
    const float* W_i0  = (const float*)d_in[1];
    const float* b_i0  = (const float*)d_in[2];
    const float* W_h0  = (const float*)d_in[3];
    const float* b_hn0 = (const float*)d_in[4];
    const float* W_i1  = (const float*)d_in[5];
    const float* b_i1  = (const float*)d_in[6];
    const float* W_h1  = (const float*)d_in[7];
    const float* b_hn1 = (const float*)d_in[8];
    const float* W_out = (const float*)d_in[9];
    const float* b_out = (const float*)d_in[10];

    float* out = (float*)d_out;               // [64,512]
    float* c0  = out + 64 * 512;              // [64,512]
    float* c1  = c0 + 64 * 512;               // [64,512]

    cudaFuncSetAttribute(gru_rec, cudaFuncAttributeMaxDynamicSharedMemorySize, SMEM_R);

    float* xg;  cudaGetSymbolAddress((void**)&xg, g_xg);
    float* y0;  cudaGetSymbolAddress((void**)&y0, g_y0);

    dim3 ggrid(G3 / 128, (BB * TT) / 128);

    // Layer 0
    gemm_tf32<<<ggrid, 256>>>(x, W_i0, b_i0, xg, 256);
    gru_rec<<<128, 256, SMEM_R>>>(W_h0, b_hn0, xg, y0, c0, 1);
    // Layer 1
    gemm_tf32<<<ggrid, 256>>>(y0, W_i1, b_i1, xg, 512);
    gru_rec<<<128, 256, SMEM_R>>>(W_h1, b_hn1, xg, y0 /*last-step tanh*/, c1, 0);
    // Dense head
    dense_k<<<128, 256>>>(y0, W_out, b_out, out);
}

// round 14
// speedup vs baseline: 2.5987x; 2.5987x over previous
#include <cuda_runtime.h>
#include <cuda_fp16.h>
#include <cstdint>
#include <math.h>

#define BB 64
#define TT 1024
#define HH 512
#define G3 1536
#define HP16 536   // half-element row pitch for staged h (1072B: conflict-free row offsets)

// ---------------- scratch (device globals; no runtime allocation) ----------------
__device__ float g_xg[(size_t)BB * TT * G3];   // [B*T][1536] packed input-gate projections
__device__ float g_y0[(size_t)BB * TT * HH];   // [B*T][512] layer-0 tanh outputs
__device__ __half g_hhi[2][BB * HH];           // ping-pong hidden state, fp16 hi plane
__device__ __half g_hlo[2][BB * HH];           // ping-pong hidden state, fp16 lo plane
__device__ unsigned g_sub[4][8][32];           // sub-counters: [bg][kc][pad to 128B]
__device__ unsigned g_done[4];                 // per-group completion counter

// ---------------- tf32 helpers (phase A) ----------------
__device__ __forceinline__ uint32_t to_tf32(float x) {
    uint32_t r;
    asm("cvt.rna.tf32.f32 %0, %1;" : "=r"(r) : "f"(x));
    return r;
}
#define MMA_TF32(d, a, b)                                                        \
    asm volatile("mma.sync.aligned.m16n8k8.row.col.f32.tf32.tf32.f32 "           \
                 "{%0,%1,%2,%3},{%4,%5,%6,%7},{%8,%9},{%0,%1,%2,%3};"            \
                 : "+f"((d)[0]), "+f"((d)[1]), "+f"((d)[2]), "+f"((d)[3])        \
                 : "r"((a)[0]), "r"((a)[1]), "r"((a)[2]), "r"((a)[3]),           \
                   "r"((b)[0]), "r"((b)[1]))

// ---------------- fp16 mma helper (phase R) ----------------
#define MMA_F16(d, a, b)                                                         \
    asm volatile("mma.sync.aligned.m16n8k16.row.col.f32.f16.f16.f32 "            \
                 "{%0,%1,%2,%3},{%4,%5,%6,%7},{%8,%9},{%0,%1,%2,%3};"            \
                 : "+f"((d)[0]), "+f"((d)[1]), "+f"((d)[2]), "+f"((d)[3])        \
                 : "r"((a)[0]), "r"((a)[1]), "r"((a)[2]), "r"((a)[3]),           \
                   "r"((b)[0]), "r"((b)[1]))

__device__ __forceinline__ unsigned poll_acq(const unsigned* p) {
    unsigned v;
    asm volatile("ld.acquire.gpu.global.u32 %0, [%1];" : "=r"(v) : "l"(p) : "memory");
    return v;
}
// release-ordered increment: fence folded into the reduction op
__device__ __forceinline__ void red_release_add(unsigned* p, unsigned v) {
    asm volatile("red.release.gpu.global.add.u32 [%0], %1;" :: "l"(p), "r"(v) : "memory");
}

// split a float2 into fp16x2 hi and lo (two-term split; residual exact)
__device__ __forceinline__ void split2(float2 v, uint32_t& hi, uint32_t& lo) {
    __half2 h2 = __floats2half2_rn(v.x, v.y);
    float2 hf = __half22float2(h2);
    __half2 l2 = __floats2half2_rn(v.x - hf.x, v.y - hf.y);
    hi = *(uint32_t*)&h2;
    lo = *(uint32_t*)&l2;
}

// ---------------- phase A: C[M,1536] = A[M,K] @ W[K,1536] + bias (tf32 MMA) ----------------
// Register prefetch + smem double-buffer: one __syncthreads per K-tile.
__global__ __launch_bounds__(256) void gemm_tf32(
    const float* __restrict__ A, const float* __restrict__ W,
    const float* __restrict__ bias, float* __restrict__ C, int K)
{
    __shared__ uint32_t As[2][128][20];
    __shared__ uint32_t Bs[2][16][136];

    const int tid = threadIdx.x;
    const int lane = tid & 31;
    const int wid = tid >> 5;
    const int wm = wid & 1;
    const int wn = wid >> 1;
    const int g = lane >> 2;
    const int c = lane & 3;
    const int bm = blockIdx.y * 128;
    const int bn = blockIdx.x * 128;

    const int ar = tid >> 1;
    const int ak = (tid & 1) * 8;
    const int br = tid >> 4;
    const int bc = (tid & 15) * 8;

    float acc[4][4][4];
#pragma unroll
    for (int mt = 0; mt < 4; ++mt)
#pragma unroll
        for (int nt = 0; nt < 4; ++nt)
#pragma unroll
            for (int i = 0; i < 4; ++i) acc[mt][nt][i] = 0.f;

    const float* ap = &A[(size_t)(bm + ar) * K + ak];
    const float* wp = &W[(size_t)br * G3 + bn + bc];

    float4 a0 = *(const float4*)&ap[0];
    float4 a1 = *(const float4*)&ap[4];
    float4 b0 = *(const float4*)&wp[0];
    float4 b1 = *(const float4*)&wp[4];

    As[0][ar][ak + 0] = to_tf32(a0.x); As[0][ar][ak + 1] = to_tf32(a0.y);
    As[0][ar][ak + 2] = to_tf32(a0.z); As[0][ar][ak + 3] = to_tf32(a0.w);
    As[0][ar][ak + 4] = to_tf32(a1.x); As[0][ar][ak + 5] = to_tf32(a1.y);
    As[0][ar][ak + 6] = to_tf32(a1.z); As[0][ar][ak + 7] = to_tf32(a1.w);
    Bs[0][br][bc + 0] = to_tf32(b0.x); Bs[0][br][bc + 1] = to_tf32(b0.y);
    Bs[0][br][bc + 2] = to_tf32(b0.z); Bs[0][br][bc + 3] = to_tf32(b0.w);
    Bs[0][br][bc + 4] = to_tf32(b1.x); Bs[0][br][bc + 5] = to_tf32(b1.y);
    Bs[0][br][bc + 6] = to_tf32(b1.z); Bs[0][br][bc + 7] = to_tf32(b1.w);
    __syncthreads();

    for (int k0 = 0; k0 < K; k0 += 16) {
        const int buf = (k0 >> 4) & 1;
        const int nxt = buf ^ 1;
        const bool have_next = (k0 + 16 < K);

        if (have_next) {
            a0 = *(const float4*)&ap[k0 + 16];
            a1 = *(const float4*)&ap[k0 + 20];
            b0 = *(const float4*)&wp[(size_t)(k0 + 16) * G3];
            b1 = *(const float4*)&wp[(size_t)(k0 + 16) * G3 + 4];
        }

#pragma unroll
        for (int kk = 0; kk < 2; ++kk) {
            uint32_t afr[4][4];
#pragma unroll
            for (int mt = 0; mt < 4; ++mt) {
                int arow = wm * 64 + mt * 16 + g;
                afr[mt][0] = As[buf][arow][kk * 8 + c];
                afr[mt][1] = As[buf][arow + 8][kk * 8 + c];
                afr[mt][2] = As[buf][arow][kk * 8 + c + 4];
                afr[mt][3] = As[buf][arow + 8][kk * 8 + c + 4];
            }
            uint32_t bfr[4][2];
#pragma unroll
            for (int nt = 0; nt < 4; ++nt) {
                int bcol = wn * 32 + nt * 8 + g;
                bfr[nt][0] = Bs[buf][kk * 8 + c][bcol];
                bfr[nt][1] = Bs[buf][kk * 8 + c + 4][bcol];
            }
#pragma unroll
            for (int mt = 0; mt < 4; ++mt)
#pragma unroll
                for (int nt = 0; nt < 4; ++nt)
                    MMA_TF32(acc[mt][nt], afr[mt], bfr[nt]);
        }

        if (have_next) {
            As[nxt][ar][ak + 0] = to_tf32(a0.x); As[nxt][ar][ak + 1] = to_tf32(a0.y);
            As[nxt][ar][ak + 2] = to_tf32(a0.z); As[nxt][ar][ak + 3] = to_tf32(a0.w);
            As[nxt][ar][ak + 4] = to_tf32(a1.x); As[nxt][ar][ak + 5] = to_tf32(a1.y);
            As[nxt][ar][ak + 6] = to_tf32(a1.z); As[nxt][ar][ak + 7] = to_tf32(a1.w);
            Bs[nxt][br][bc + 0] = to_tf32(b0.x); Bs[nxt][br][bc + 1] = to_tf32(b0.y);
            Bs[nxt][br][bc + 2] = to_tf32(b0.z); Bs[nxt][br][bc + 3] = to_tf32(b0.w);
            Bs[nxt][br][bc + 4] = to_tf32(b1.x); Bs[nxt][br][bc + 5] = to_tf32(b1.y);
            Bs[nxt][br][bc + 6] = to_tf32(b1.z); Bs[nxt][br][bc + 7] = to_tf32(b1.w);
            __syncthreads();
        }
    }

#pragma unroll
    for (int mt = 0; mt < 4; ++mt) {
        int r0 = bm + wm * 64 + mt * 16 + g;
#pragma unroll
        for (int nt = 0; nt < 4; ++nt) {
            int col = bn + wn * 32 + nt * 8 + 2 * c;
            float2 bv = *(const float2*)&bias[col];
            float2 v0 = make_float2(acc[mt][nt][0] + bv.x, acc[mt][nt][1] + bv.y);
            float2 v1 = make_float2(acc[mt][nt][2] + bv.x, acc[mt][nt][3] + bv.y);
            *(float2*)&C[(size_t)r0 * G3 + col] = v0;
            *(float2*)&C[(size_t)(r0 + 8) * G3 + col] = v1;
        }
    }
}

// ---------------- phase R: persistent GRU recurrence (fp16-split tensor cores) ----------------
// 128 CTAs = 4 batch-groups(16 batches) x 32 col-groups(16 output cols = 48 gate cols).
// Sync: 8 sub-counters per group (128B apart). Producer jg REDs sub jg>>2.
// Consumer warp kc polls ONE address (sub kc = its 4 producers), lane-0 ld.acquire.
// h exchanged as fp16 hi/lo planes (split done producer-side; bit-identical math).
#define SMEM_R ((2 * 16 * HP16) * 2 + (8 * 16 * 48) * 4)

__device__ __forceinline__ float sigf(float x) {
    return __fdividef(1.f, 1.f + __expf(-x));
}

__global__ __launch_bounds__(256, 1) void gru_rec(
    const float* __restrict__ Wh,    // [512][1536]
    const float* __restrict__ bhn,   // [512]
    const float* __restrict__ xg,    // [B*T][1536]
    float* __restrict__ y,           // [B*T][512] (y_all=1) or [B][512] last tanh (y_all=0)
    float* __restrict__ cfin,        // [64*512] final raw h
    int y_all)
{
    extern __shared__ __align__(16) char smraw[];
    __half* hs_hi = (__half*)smraw;                    // [16][HP16]
    __half* hs_lo = hs_hi + 16 * HP16;                 // [16][HP16]
    float*  red   = (float*)(hs_lo + 16 * HP16);       // [8 kc][16 row][48 col]

    const int tid = threadIdx.x;
    const int cta = blockIdx.x;
    const int bg = cta >> 5;               // batch group 0..3
    const int jg = cta & 31;               // col group 0..31
    const int b0 = bg * 16;
    const int j0 = jg * 16;

    const int lane = tid & 31;
    const int kc = tid >> 5;               // warp id = K-chunk 0..7
    const int kb = kc * 64;
    const int g = lane >> 2;               // mma group row
    const int c = lane & 3;                // mma group col
    const int eb = tid >> 4;               // elementwise batch 0..15
    const int ej = tid & 15;               // elementwise col
    const float bh_n = bhn[j0 + ej];
    unsigned* my_pub  = &g_sub[bg][jg >> 2][0];   // producer target
    const unsigned* my_wait = &g_sub[bg][kc][0];  // this warp's wait address

    // ---- Precompute W_h fragments (hi/lo fp16) into registers.
    uint32_t bhi[6][4][2], blo[6][4][2];
#pragma unroll
    for (int nt = 0; nt < 6; ++nt) {
        int cl = nt * 8 + g;               // local col 0..47
        int wcol = (cl >> 4) * HH + j0 + (cl & 15);
#pragma unroll
        for (int kt = 0; kt < 4; ++kt) {
            int kbase = kb + kt * 16;
            float w0 = Wh[(size_t)(kbase + 2 * c) * G3 + wcol];
            float w1 = Wh[(size_t)(kbase + 2 * c + 1) * G3 + wcol];
            float w2 = Wh[(size_t)(kbase + 2 * c + 8) * G3 + wcol];
            float w3 = Wh[(size_t)(kbase + 2 * c + 9) * G3 + wcol];
            split2(make_float2(w0, w1), bhi[nt][kt][0], blo[nt][kt][0]);
            split2(make_float2(w2, w3), bhi[nt][kt][1], blo[nt][kt][1]);
        }
    }

    // Produce h^(0) = 0 for our own slice, publish like a normal step.
    {
        size_t hi0 = (size_t)(b0 + eb) * HH + j0 + ej;
        g_hhi[0][hi0] = __float2half(0.f);
        g_hlo[0][hi0] = __float2half(0.f);
    }
    __syncthreads();
    if (tid == 0) red_release_add(my_pub, 1u);

    // Warp-private staging: warp kc stages [all 16 rows][kb..kb+64) of hi+lo.
    const int sb = lane >> 1;
    const int sk = kb + (lane & 1) * 32;

    for (int t = 0; t < TT; ++t) {
        const __half* hin_hi = g_hhi[t & 1];
        const __half* hin_lo = g_hlo[t & 1];
        __half* hout_hi = g_hhi[(t + 1) & 1];
        __half* hout_lo = g_hlo[(t + 1) & 1];

        // xg prefetch (independent of h) — issued before the poll.
        size_t xi = ((size_t)(b0 + eb) * TT + t) * G3 + j0 + ej;
        float xr = __ldcs(&xg[xi]);
        float xz = __ldcs(&xg[xi + 512]);
        float xn = __ldcs(&xg[xi + 1024]);

        // Per-warp wait: ONE acquire-poll address covering this warp's 4 producers.
        unsigned target = 4u * (unsigned)(t + 1);
        if (lane == 0) {
            while (poll_acq(my_wait) < target) { }
        }
        __syncwarp();

        // Warp-private h staging (hi+lo, 64B each per lane).
        {
            const size_t gb = (size_t)(b0 + sb) * HH + sk;
            uint4 vh0 = __ldcg((const uint4*)&hin_hi[gb]);
            uint4 vh1 = __ldcg((const uint4*)&hin_hi[gb + 8]);
            uint4 vh2 = __ldcg((const uint4*)&hin_hi[gb + 16]);
            uint4 vh3 = __ldcg((const uint4*)&hin_hi[gb + 24]);
            uint4 vl0 = __ldcg((const uint4*)&hin_lo[gb]);
            uint4 vl1 = __ldcg((const uint4*)&hin_lo[gb + 8]);
            uint4 vl2 = __ldcg((const uint4*)&hin_lo[gb + 16]);
            uint4 vl3 = __ldcg((const uint4*)&hin_lo[gb + 24]);
            __half* dh = &hs_hi[sb * HP16 + sk];
            __half* dl = &hs_lo[sb * HP16 + sk];
            *(uint4*)&dh[0]  = vh0; *(uint4*)&dh[8]  = vh1;
            *(uint4*)&dh[16] = vh2; *(uint4*)&dh[24] = vh3;
            *(uint4*)&dl[0]  = vl0; *(uint4*)&dl[8]  = vl1;
            *(uint4*)&dl[16] = vl2; *(uint4*)&dl[24] = vl3;
        }
        __syncwarp();

        // ---- tensor-core partial GEMM over K-chunk 64: acc[6 n-tiles][4].
        float acc[6][4];
#pragma unroll
        for (int nt = 0; nt < 6; ++nt)
#pragma unroll
            for (int i = 0; i < 4; ++i) acc[nt][i] = 0.f;

#pragma unroll
        for (int kt = 0; kt < 4; ++kt) {
            int k0 = kb + kt * 16;
            uint32_t ahi[4], alo[4];
            ahi[0] = *(const uint32_t*)&hs_hi[g * HP16 + k0 + 2 * c];
            ahi[1] = *(const uint32_t*)&hs_hi[(g + 8) * HP16 + k0 + 2 * c];
            ahi[2] = *(const uint32_t*)&hs_hi[g * HP16 + k0 + 2 * c + 8];
            ahi[3] = *(const uint32_t*)&hs_hi[(g + 8) * HP16 + k0 + 2 * c + 8];
            alo[0] = *(const uint32_t*)&hs_lo[g * HP16 + k0 + 2 * c];
            alo[1] = *(const uint32_t*)&hs_lo[(g + 8) * HP16 + k0 + 2 * c];
            alo[2] = *(const uint32_t*)&hs_lo[g * HP16 + k0 + 2 * c + 8];
            alo[3] = *(const uint32_t*)&hs_lo[(g + 8) * HP16 + k0 + 2 * c + 8];
#pragma unroll
            for (int nt = 0; nt < 6; ++nt) {
                MMA_F16(acc[nt], ahi, bhi[nt][kt]);
                MMA_F16(acc[nt], ahi, blo[nt][kt]);
                MMA_F16(acc[nt], alo, bhi[nt][kt]);
            }
        }

        // Write K-split partials.
#pragma unroll
        for (int nt = 0; nt < 6; ++nt) {
            int colb = nt * 8 + 2 * c;
            *(float2*)&red[(kc * 16 + g) * 48 + colb] =
                make_float2(acc[nt][0], acc[nt][1]);
            *(float2*)&red[(kc * 16 + g + 8) * 48 + colb] =
                make_float2(acc[nt][2], acc[nt][3]);
        }
        __syncthreads();

        // Elementwise GRU update: thread = (eb, ej).
        float hr = 0.f, hz = 0.f, hn = 0.f;
#pragma unroll
        for (int q = 0; q < 8; ++q) {
            const float* rp = &red[(q * 16 + eb) * 48];
            hr += rp[ej]; hz += rp[16 + ej]; hn += rp[32 + ej];
        }
        float h_old = __half2float(hs_hi[eb * HP16 + j0 + ej]) +
                      __half2float(hs_lo[eb * HP16 + j0 + ej]);
        float r = sigf(xr + hr);
        float z = sigf(xz + hz);
        float n = tanhf(xn + r * (hn + bh_n));
        float hnew = (1.f - z) * n + z * h_old;

        // Producer-side hi/lo split (bit-identical to consumer-side split of fp32 h).
        __half hh = __float2half_rn(hnew);
        __half hl = __float2half_rn(hnew - __half2float(hh));
        size_t ho = (size_t)(b0 + eb) * HH + j0 + ej;
        hout_hi[ho] = hh;
        hout_lo[ho] = hl;

        // Publish h^(t+1) (skip the dead final publish), then non-critical stores.
        __syncthreads();
        if (t < TT - 1 && tid == 0) red_release_add(my_pub, 1u);

        if (y_all) {
            y[((size_t)(b0 + eb) * TT + t) * HH + j0 + ej] = tanhf(hnew);
        } else if (t == TT - 1) {
            y[(size_t)(b0 + eb) * HH + j0 + ej] = tanhf(hnew);
        }
        if (t == TT - 1)
            cfin[(size_t)(b0 + eb) * HH + j0 + ej] = hnew;
    }

    // ---- reset protocol for graph replay ----
    if (tid == 0) {
        red_release_add(&g_done[bg], 1u);
        if (jg == 0) {
            while (poll_acq(&g_done[bg]) < 32u) { }
            for (int q = 0; q < 8; ++q) g_sub[bg][q][0] = 0u;
            __threadfence();
            atomicExch(&g_done[bg], 0u);
        }
    }
}

// ---------------- dense head: out = tanh(ylast @ W_out + b_out) ----------------
__global__ __launch_bounds__(256) void dense_k(
    const float* __restrict__ yl,
    const float* __restrict__ W,
    const float* __restrict__ b,
    float* __restrict__ out)
{
    int gid = blockIdx.x * 256 + threadIdx.x;
    int bb = gid >> 9;
    int j  = gid & 511;
    const float* xr = yl + (size_t)bb * 512;
    float s = b[j];
#pragma unroll 4
    for (int k = 0; k < 512; k += 4) {
        float4 xv = *(const float4*)&xr[k];
        s = fmaf(xv.x, W[(size_t)(k + 0) * 512 + j], s);
        s = fmaf(xv.y, W[(size_t)(k + 1) * 512 + j], s);
        s = fmaf(xv.z, W[(size_t)(k + 2) * 512 + j], s);
        s = fmaf(xv.w, W[(size_t)(k + 3) * 512 + j], s);
    }
    out[gid] = tanhf(s);
}

// ---------------- launch ----------------
extern "C" void kernel_launch(void* const* d_in, const int* in_sizes, int n_in,
                              void* d_out, int out_size) {
    const float* x     = (const float*)d_in[0];
    const float* W_i0  = (const float*)d_in[1];
    const float* b_i0  = (const float*)d_in[2];
    const float* W_h0  = (const float*)d_in[3];
    const float* b_hn0 = (const float*)d_in[4];
    const float* W_i1  = (const float*)d_in[5];
    const float* b_i1  = (const float*)d_in[6];
    const float* W_h1  = (const float*)d_in[7];
    const float* b_hn1 = (const float*)d_in[8];
    const float* W_out = (const float*)d_in[9];
    const float* b_out = (const float*)d_in[10];

    float* out = (float*)d_out;               // [64,512]
    float* c0  = out + 64 * 512;              // [64,512]
    float* c1  = c0 + 64 * 512;               // [64,512]

    cudaFuncSetAttribute(gru_rec, cudaFuncAttributeMaxDynamicSharedMemorySize, SMEM_R);

    float* xg;  cudaGetSymbolAddress((void**)&xg, g_xg);
    float* y0;  cudaGetSymbolAddress((void**)&y0, g_y0);

    dim3 ggrid(G3 / 128, (BB * TT) / 128);

    // Layer 0
    gemm_tf32<<<ggrid, 256>>>(x, W_i0, b_i0, xg, 256);
    gru_rec<<<128, 256, SMEM_R>>>(W_h0, b_hn0, xg, y0, c0, 1);
    // Layer 1
    gemm_tf32<<<ggrid, 256>>>(y0, W_i1, b_i1, xg, 512);
    gru_rec<<<128, 256, SMEM_R>>>(W_h1, b_hn1, xg, y0 /*last-step tanh*/, c1, 0);
    // Dense head
    dense_k<<<128, 256>>>(y0, W_out, b_out, out);
}